// round 6
// baseline (speedup 1.0000x reference)
#include <cuda_runtime.h>
#include <cmath>

// net_LSTM_21534966022336: T=4096, B=8192, I=H=1 -> 8192 independent scalar
// LSTM chains; latency-bound. Calibrated model: per-step = 2L + 26,
// L ~= 39 cyc effective MUFU.TANH RAW. This round removes the i-gate from
// the MUFU port: tanh(a_i) via fixed-latency FFMA polynomial (odd deg-15,
// coefficients fit at runtime in fp64 against device tanh()), so only f,g
// occupy critical MUFU slots and the terminal fma fires at L+17, not L+25.

#ifndef LSTM_T
#define LSTM_T 4096
#endif
#ifndef LSTM_B
#define LSTM_B 8192
#endif

__device__ __forceinline__ float tanh_approx(float v) {
    float y;
    asm("tanh.approx.f32 %0, %1;" : "=f"(y) : "f"(v));
    return y;
}

// One-time per-thread fit: tanh(a) ~= a * q(a^2) on [-3,3], q = sum d_m y^m,
// deg 7 in y. Interpolate q at 8 Chebyshev-spaced nodes; 8x8 Vandermonde
// solved by fp64 Gaussian elimination (no pivot; nodes ascending => fine).
__device__ void fit_tanh_poly(float* df) {
    const double R = 3.0;
    const double nodes[8] = {0.098017, 0.290285, 0.471397, 0.634393,
                             0.773010, 0.881921, 0.956940, 0.995185};
    double A[8][9];
#pragma unroll
    for (int j = 0; j < 8; ++j) {
        const double a = R * nodes[j];
        const double y = a * a;
        double p = 1.0;
#pragma unroll
        for (int m = 0; m < 8; ++m) { A[j][m] = p; p *= y; }
        A[j][8] = tanh(a) / a;          // fp64 oracle, exact to ~1ulp
    }
#pragma unroll
    for (int k = 0; k < 8; ++k) {
        const double inv = 1.0 / A[k][k];
#pragma unroll
        for (int i = 0; i < 8; ++i) {
            if (i > k) {
                const double f = A[i][k] * inv;
#pragma unroll
                for (int m = 0; m < 9; ++m) A[i][m] -= f * A[k][m];
            }
        }
    }
    double d[8];
#pragma unroll
    for (int k = 7; k >= 0; --k) {
        double s = A[k][8];
#pragma unroll
        for (int m = 0; m < 8; ++m)
            if (m > k) s -= A[k][m] * d[m];
        d[k] = s / A[k][k];
    }
#pragma unroll
    for (int m = 0; m < 8; ++m) df[m] = (float)d[m];
}

__global__ void __launch_bounds__(128, 1)
lstm_scalar_chain_kernel(const float* __restrict__ x,
                         const float* __restrict__ h0,
                         const float* __restrict__ c0,
                         const float* __restrict__ w_ih,
                         const float* __restrict__ w_hh,
                         float* __restrict__ out,
                         int out_size) {
    const int b = blockIdx.x * blockDim.x + threadIdx.x;
    if (b >= LSTM_B) return;

    // Runtime-fit polynomial coefficients (identical across threads).
    float d[8];
    fit_tanh_poly(d);
    const float d0 = d[0], d1 = d[1], d2 = d[2], d3 = d[3];
    const float d4 = d[4], d5 = d[5], d6 = d[6], d7 = d[7];

    // Pre-scaled shared scalar weights (gate order i, f, g, o).
    const float wi_i = 0.50f * w_ih[0];
    const float wi_f = 0.50f * w_ih[1];
    const float wi_g =         w_ih[2];
    const float wi_o = 0.50f * w_ih[3];
    const float wh_i = 0.25f * w_hh[0];
    const float wh_f = 0.25f * w_hh[1];
    const float wh_g = 0.50f * w_hh[2];
    const float wh_o = 0.25f * w_hh[3];

    // Seed: tc*(1+to) = 2*h0 -> tc = 2*h0, to = 0 (exact).
    float tc = 2.0f * h0[b];
    float to = 0.0f;
    float c  = c0[b];

    const float* xp = x + b;
    float*       op = out + b;

    // 4-phase ring of 8-wide x buffers: 32 steps resident, reloaded in place
    // right after consumption (prefetch distance = 24 steps, no copies).
    float xr[32];
#pragma unroll
    for (int u = 0; u < 32; ++u) xr[u] = xp[u * LSTM_B];

    for (int t0 = 0; t0 < LSTM_T; t0 += 32) {
#pragma unroll
        for (int ph = 0; ph < 4; ++ph) {
#pragma unroll
            for (int u = 0; u < 8; ++u) {
                const int t = t0 + ph * 8 + u;
                const float xv = xr[ph * 8 + u];

                // Off-path terms (to-dependent scales hide in tanh(c) wait).
                const float xi = xv * wi_i;
                const float xf = xv * wi_f;
                const float xg = xv * wi_g;
                const float xo = xv * wi_o;

                const float si_ = fmaf(to, wh_i, wh_i);
                const float sf  = fmaf(to, wh_f, wh_f);
                const float sg  = fmaf(to, wh_g, wh_g);
                const float so  = fmaf(to, wh_o, wh_o);

                const float hc = 0.5f * c;

                // Critical fmas after tc lands; i first (feeds the poly).
                const float ai = fmaf(tc, si_, xi);
                const float af = fmaf(tc, sf, xf);
                const float ag = fmaf(tc, sg, xg);
                const float ao = fmaf(tc, so, xo);

                // MUFU: f first (feeds v), g second (terminal), o off-path.
                const float tf  = tanh_approx(af);
                const float tg  = tanh_approx(ag);
                const float to2 = tanh_approx(ao);

                // Polynomial tanh for the i-gate (fixed-latency, fma pipe).
                // Clamps make the tail exactly flat at +-tanh(3).
                const float yy  = ai * ai;
                const float yc  = fminf(yy, 9.0f);
                const float acl = fmaxf(fminf(ai, 3.0f), -3.0f);  // ALU, off-path
                const float e0  = fmaf(d1, yc, d0);
                const float e1  = fmaf(d3, yc, d2);
                const float e2  = fmaf(d5, yc, d4);
                const float e3  = fmaf(d7, yc, d6);
                const float y2  = yc * yc;
                const float g0  = fmaf(e1, y2, e0);
                const float g1  = fmaf(e3, y2, e2);
                const float y4  = y2 * y2;
                const float qq  = fmaf(g1, y4, g0);
                const float ti  = acl * qq;                        // tanh(a_i)

                // Combine: c' = sigmoid(f)*c + sigmoid(i)*tanh(g)
                //            = fma(tg, k, v), terminal on tg (2nd MUFU).
                const float v = fmaf(tf, hc, hc);      // c * sigmoid(f)
                const float k = fmaf(ti, 0.5f, 0.5f);  // sigmoid(i)
                c = fmaf(tg, k, v);

                const float tc2 = tanh_approx(c);

                // h = sigmoid(o)*tanh(c); off the critical path.
                const float sho = fmaf(to2, 0.5f, 0.5f);
                op[t * LSTM_B] = tc2 * sho;

                tc = tc2;
                to = to2;
            }
            // Reload this phase's buffer for t0+32 (clamped dummy at tail).
#pragma unroll
            for (int u = 0; u < 8; ++u) {
                int t = t0 + 32 + ph * 8 + u;
                t = (t < LSTM_T) ? t : (LSTM_T - 1);
                xr[ph * 8 + u] = xp[t * LSTM_B];
            }
        }
    }

    // h_n, c_n appended after out (tuple flattening order).
    if (out_size >= LSTM_T * LSTM_B + 2 * LSTM_B) {
        out[LSTM_T * LSTM_B + b]          = tc * fmaf(to, 0.5f, 0.5f);
        out[LSTM_T * LSTM_B + LSTM_B + b] = c;
    }
}

extern "C" void kernel_launch(void* const* d_in, const int* in_sizes, int n_in,
                              void* d_out, int out_size) {
    const float* x    = (const float*)d_in[0];
    const float* h0   = (const float*)d_in[1];
    const float* c0   = (const float*)d_in[2];
    const float* w_ih = (const float*)d_in[3];
    const float* w_hh = (const float*)d_in[4];
    float* out = (float*)d_out;

    const int threads = 128;
    const int blocks  = (LSTM_B + threads - 1) / threads;
    lstm_scalar_chain_kernel<<<blocks, threads>>>(x, h0, c0, w_ih, w_hh, out, out_size);
}